// round 7
// baseline (speedup 1.0000x reference)
#include <cuda_runtime.h>
#include <cuda_fp16.h>
#include <cstdint>

// ---------------------------------------------------------------------------
// BasicAttention B=8, C=1024, L=2048, A=128 — fp16 mma.m16n8k16.
// 128x128x64 CTA tile, 4 warps, 64x64 warp tile (MMA:LDSM = 4:1).
//   xTh  [2048,1024] = half(x^T)
//   kqT  [2048,256]  = xTh · W2^T + b2(col)
//   E2   [2048,2048] = exp((qT_m · kT_l)/1024)    half [m][l]
//   rcp[l] = 1 / sum_m E2[m,l]
//   y'   [1024,2048] = (Wp · x)[d,l] * rcp[l]     half
//   out  [1024,2048] = y' · E2^T + bp(row)        f32
// ---------------------------------------------------------------------------

#define BATCH 8
#define CDIM 1024
#define LDIM 2048

__device__ __half g_w2h[256 * 1024];
__device__ float  g_b2[256];
__device__ __half g_wph[CDIM * CDIM];
__device__ __half g_xTh[BATCH * LDIM * CDIM];
__device__ __half g_kqT[BATCH * LDIM * 256];
__device__ __half g_E2[(long long)BATCH * LDIM * LDIM];
__device__ float  g_part[BATCH * 16 * LDIM];
__device__ float  g_rcp[BATCH * LDIM];
__device__ __half g_y[BATCH * CDIM * LDIM];

#define BM 128
#define BN 128
#define BK 64
#define KSTRIDE 72
#define TILE_HALVES (128 * KSTRIDE)

#define CP_ASYNC16(dst, src) \
    asm volatile("cp.async.cg.shared.global [%0], [%1], 16;" :: "r"(dst), "l"(src))
#define CP_COMMIT() asm volatile("cp.async.commit_group;")
#define CP_WAIT0()  asm volatile("cp.async.wait_group 0;")

#define LDSM4(r0, r1, r2, r3, addr) \
    asm volatile("ldmatrix.sync.aligned.m8n8.x4.shared.b16 {%0,%1,%2,%3}, [%4];" \
                 : "=r"(r0), "=r"(r1), "=r"(r2), "=r"(r3) : "r"(addr))

__device__ __forceinline__ void mma_f16(float* c, const uint32_t* a, const uint32_t* b) {
    asm volatile(
        "mma.sync.aligned.m16n8k16.row.col.f32.f16.f16.f32 "
        "{%0,%1,%2,%3}, {%4,%5,%6,%7}, {%8,%9}, {%0,%1,%2,%3};"
        : "+f"(c[0]), "+f"(c[1]), "+f"(c[2]), "+f"(c[3])
        : "r"(a[0]), "r"(a[1]), "r"(a[2]), "r"(a[3]), "r"(b[0]), "r"(b[1]));
}

// TN fp16 GEMM: D[i,j] = sum_k A[i*lda+k] * B[j*ldb+k]
// EPI: 1 half+bias[col] | 2 half=exp(v/1024) | 3 f32+bias[row] | 4 half*scale[col](per-batch)
template <int EPI, typename OT>
__global__ void __launch_bounds__(128, 2) hgemm_kernel(
    const __half* __restrict__ A, const __half* __restrict__ B,
    const float* __restrict__ bias, OT* __restrict__ C,
    int K, int lda, int ldb, int ldc,
    long long sA, long long sB, long long sC)
{
    extern __shared__ __half sm[];
    __half* As = sm;
    __half* Bs = sm + 2 * TILE_HALVES;

    const int bz = blockIdx.z;
    A += (long long)bz * sA;
    B += (long long)bz * sB;
    C += (long long)bz * sC;
    if (EPI == 4) bias += (long long)bz * LDIM;

    const int tid  = threadIdx.x;
    const int lane = tid & 31;
    const int wid  = tid >> 5;          // 0..3
    const int warp_m = wid >> 1;        // 0..1 -> 64-row slab
    const int warp_n = wid & 1;         // 0..1 -> 64-col slab
    const int g = lane >> 2;
    const int t = lane & 3;

    const int row0 = blockIdx.y * BM;
    const int col0 = blockIdx.x * BN;

    const uint32_t asb = (uint32_t)__cvta_generic_to_shared(As);
    const uint32_t bsb = (uint32_t)__cvta_generic_to_shared(Bs);

    // ldmatrix lane addressing
    const int aRow = warp_m * 64 + ((lane >> 3) & 1) * 8 + (lane & 7);
    const int aK   = ((lane >> 4) & 1) * 8;
    const int bRow = warp_n * 64 + ((lane >> 4) & 1) * 8 + (lane & 7);
    const int bK   = ((lane >> 3) & 1) * 8;

    float acc[4][8][4];
#pragma unroll
    for (int mt = 0; mt < 4; ++mt)
#pragma unroll
        for (int nt = 0; nt < 8; ++nt)
#pragma unroll
            for (int i = 0; i < 4; ++i) acc[mt][nt][i] = 0.0f;

    const int ntiles = K / BK;

    auto issue_loads = [&](int k0, int buf) {
        const uint32_t ab = asb + (uint32_t)(buf * TILE_HALVES) * 2;
        const uint32_t bb = bsb + (uint32_t)(buf * TILE_HALVES) * 2;
#pragma unroll
        for (int i = 0; i < 8; ++i) {     // A: 128 rows x 8 chunks of 8 halves
            int idx = i * 128 + tid;
            int r = idx >> 3, c = idx & 7;
            const __half* src = A + (long long)(row0 + r) * lda + k0 + c * 8;
            CP_ASYNC16(ab + (uint32_t)(r * KSTRIDE + c * 8) * 2, src);
        }
#pragma unroll
        for (int i = 0; i < 8; ++i) {     // B: 128 rows x 8 chunks
            int idx = i * 128 + tid;
            int r = idx >> 3, c = idx & 7;
            const __half* src = B + (long long)(col0 + r) * ldb + k0 + c * 8;
            CP_ASYNC16(bb + (uint32_t)(r * KSTRIDE + c * 8) * 2, src);
        }
        CP_COMMIT();
    };

    issue_loads(0, 0);
    int buf = 0;

    for (int kt = 0; kt < ntiles; ++kt) {
        CP_WAIT0();
        __syncthreads();
        if (kt + 1 < ntiles) issue_loads((kt + 1) * BK, buf ^ 1);

        const uint32_t ab = asb + (uint32_t)(buf * TILE_HALVES) * 2;
        const uint32_t bb = bsb + (uint32_t)(buf * TILE_HALVES) * 2;

#pragma unroll
        for (int ks = 0; ks < BK / 16; ++ks) {
            const int kk = ks * 16;
            uint32_t af[4][4];
#pragma unroll
            for (int mt = 0; mt < 4; ++mt) {
                uint32_t addr = ab + (uint32_t)((aRow + mt * 16) * KSTRIDE + kk + aK) * 2;
                LDSM4(af[mt][0], af[mt][1], af[mt][2], af[mt][3], addr);
            }
            uint32_t bf[8][2];
#pragma unroll
            for (int p = 0; p < 4; ++p) {   // each x4 covers two 8-col n-slices
                uint32_t addr = bb + (uint32_t)((bRow + p * 16) * KSTRIDE + kk + bK) * 2;
                LDSM4(bf[2 * p][0], bf[2 * p][1], bf[2 * p + 1][0], bf[2 * p + 1][1], addr);
            }
#pragma unroll
            for (int mt = 0; mt < 4; ++mt)
#pragma unroll
                for (int nt = 0; nt < 8; ++nt)
                    mma_f16(acc[mt][nt], af[mt], bf[nt]);
        }
        __syncthreads();
        buf ^= 1;
    }

    // Epilogue: c0 (g,2t) c1 (g,2t+1) c2 (g+8,2t) c3 (g+8,2t+1)
#pragma unroll
    for (int mt = 0; mt < 4; ++mt) {
        const int rowA = row0 + warp_m * 64 + mt * 16 + g;
        float br0 = 0.f, br1 = 0.f;
        if (EPI == 3) { br0 = bias[rowA]; br1 = bias[rowA + 8]; }
#pragma unroll
        for (int nt = 0; nt < 8; ++nt) {
            const int col = col0 + warp_n * 64 + nt * 8 + 2 * t;
            float c0 = acc[mt][nt][0], c1 = acc[mt][nt][1];
            float c2 = acc[mt][nt][2], c3 = acc[mt][nt][3];
            if (EPI == 1) {
                float b0 = bias[col], b1 = bias[col + 1];
                c0 += b0; c1 += b1; c2 += b0; c3 += b1;
            } else if (EPI == 2) {
                const float s = 1.0f / 1024.0f;
                c0 = __expf(c0 * s); c1 = __expf(c1 * s);
                c2 = __expf(c2 * s); c3 = __expf(c3 * s);
            } else if (EPI == 3) {
                c0 += br0; c1 += br0; c2 += br1; c3 += br1;
            } else if (EPI == 4) {
                float s0 = bias[col], s1 = bias[col + 1];
                c0 *= s0; c1 *= s1; c2 *= s0; c3 *= s1;
            }
            if (sizeof(OT) == 2) {
                __half2* p0 = (__half2*)((__half*)C + (long long)rowA * ldc + col);
                __half2* p1 = (__half2*)((__half*)C + (long long)(rowA + 8) * ldc + col);
                *p0 = __floats2half2_rn(c0, c1);
                *p1 = __floats2half2_rn(c2, c3);
            } else {
                float2 v0 = { c0, c1 };
                float2 v1 = { c2, c3 };
                *(float2*)((float*)C + (long long)rowA * ldc + col) = v0;
                *(float2*)((float*)C + (long long)(rowA + 8) * ldc + col) = v1;
            }
        }
    }
}

// ---------------- prep / reduction kernels ----------------

__global__ void concat_w_kernel(const float* __restrict__ Wk, const float* __restrict__ bk,
                                const float* __restrict__ Wq, const float* __restrict__ bq)
{
    int i = blockIdx.x * blockDim.x + threadIdx.x;
    const int half_n = 128 * 1024;
    if (i < half_n)          g_w2h[i] = __float2half_rn(Wk[i]);
    else if (i < 2 * half_n) g_w2h[i] = __float2half_rn(Wq[i - half_n]);
    if (i < 128)             g_b2[i] = bk[i];
    else if (i < 256)        g_b2[i] = bq[i - 128];
}

__global__ void round_wp_kernel(const float* __restrict__ Wp)
{
    int i = blockIdx.x * blockDim.x + threadIdx.x;
    if (i < CDIM * CDIM) g_wph[i] = __float2half_rn(Wp[i]);
}

// x [B,1024,2048] f32 -> xTh [B,2048,1024] half
__global__ void xprep_kernel(const float* __restrict__ x)
{
    __shared__ float tile[32][33];
    const int bz = blockIdx.z;
    const float* in = x + (long long)bz * CDIM * LDIM;
    __half* xth = g_xTh + (long long)bz * LDIM * CDIM;

    int l = blockIdx.x * 32 + threadIdx.x;
    int c = blockIdx.y * 32 + threadIdx.y;
#pragma unroll
    for (int j = 0; j < 32; j += 8)
        tile[threadIdx.y + j][threadIdx.x] = in[(long long)(c + j) * LDIM + l];
    __syncthreads();
    int c2 = blockIdx.y * 32 + threadIdx.x;
    int l2 = blockIdx.x * 32 + threadIdx.y;
#pragma unroll
    for (int j = 0; j < 32; j += 8)
        xth[(long long)(l2 + j) * CDIM + c2] = __float2half_rn(tile[threadIdx.x][threadIdx.y + j]);
}

// partial column sums of E2
__global__ void __launch_bounds__(256) colsum_kernel()
{
    const int bz = blockIdx.z;
    const int l2 = blockIdx.x * 512 + threadIdx.x * 2;
    const __half* p = g_E2 + (long long)bz * LDIM * LDIM +
                      (long long)(blockIdx.y * 128) * LDIM + l2;
    float s0 = 0.f, s1 = 0.f;
#pragma unroll 4
    for (int r = 0; r < 128; ++r) {
        __half2 v = *(const __half2*)(p + (long long)r * LDIM);
        float2 f = __half22float2(v);
        s0 += f.x; s1 += f.y;
    }
    float* q = g_part + ((long long)(bz * 16 + blockIdx.y)) * LDIM + l2;
    q[0] = s0; q[1] = s1;
}

__global__ void __launch_bounds__(1024) reduce_rcp_kernel()
{
    const int bz = blockIdx.x;
#pragma unroll
    for (int h = 0; h < 2; ++h) {
        int col = threadIdx.x + h * 1024;
        float s = 0.f;
#pragma unroll
        for (int sp = 0; sp < 16; ++sp)
            s += g_part[((long long)(bz * 16 + sp)) * LDIM + col];
        g_rcp[bz * LDIM + col] = 1.0f / s;
    }
}

extern "C" void kernel_launch(void* const* d_in, const int* in_sizes, int n_in,
                              void* d_out, int out_size)
{
    const float* x  = (const float*)d_in[0];
    const float* Wk = (const float*)d_in[1];
    const float* bk = (const float*)d_in[2];
    const float* Wq = (const float*)d_in[3];
    const float* bq = (const float*)d_in[4];
    const float* Wp = (const float*)d_in[5];
    const float* bp = (const float*)d_in[6];
    float* out = (float*)d_out;

    const int SMEM = 4 * TILE_HALVES * 2;   // 73728 bytes
    cudaFuncSetAttribute(hgemm_kernel<1, __half>, cudaFuncAttributeMaxDynamicSharedMemorySize, SMEM);
    cudaFuncSetAttribute(hgemm_kernel<2, __half>, cudaFuncAttributeMaxDynamicSharedMemorySize, SMEM);
    cudaFuncSetAttribute(hgemm_kernel<3, float>,  cudaFuncAttributeMaxDynamicSharedMemorySize, SMEM);
    cudaFuncSetAttribute(hgemm_kernel<4, __half>, cudaFuncAttributeMaxDynamicSharedMemorySize, SMEM);

    __half *p_w2h, *p_wph, *p_xTh, *p_kqT, *p_E2, *p_y;
    float *p_b2, *p_rcp;
    cudaGetSymbolAddress((void**)&p_w2h, g_w2h);
    cudaGetSymbolAddress((void**)&p_b2,  g_b2);
    cudaGetSymbolAddress((void**)&p_wph, g_wph);
    cudaGetSymbolAddress((void**)&p_xTh, g_xTh);
    cudaGetSymbolAddress((void**)&p_kqT, g_kqT);
    cudaGetSymbolAddress((void**)&p_E2,  g_E2);
    cudaGetSymbolAddress((void**)&p_rcp, g_rcp);
    cudaGetSymbolAddress((void**)&p_y,   g_y);

    // 0) operand prep
    concat_w_kernel<<<(256 * 1024 + 255) / 256, 256>>>(Wk, bk, Wq, bq);
    round_wp_kernel<<<(CDIM * CDIM + 255) / 256, 256>>>(Wp);
    xprep_kernel<<<dim3(LDIM / 32, CDIM / 32, BATCH), dim3(32, 8)>>>(x);

    // 1) kqT[l,a] = xTh[l,:]·W2[a,:] + b2[a]
    hgemm_kernel<1, __half><<<dim3(256 / BN, LDIM / BM, BATCH), 128, SMEM>>>(
        p_xTh, p_w2h, p_b2, p_kqT,
        CDIM, CDIM, CDIM, 256,
        (long long)LDIM * CDIM, 0LL, (long long)LDIM * 256);

    // 2) E2[m,l] = exp((qT[m,:]·kT[l,:])/1024)   K=128, half out
    hgemm_kernel<2, __half><<<dim3(LDIM / BN, LDIM / BM, BATCH), 128, SMEM>>>(
        p_kqT + 128, p_kqT, nullptr, p_E2,
        128, 256, 256, LDIM,
        (long long)LDIM * 256, (long long)LDIM * 256, (long long)LDIM * LDIM);

    // 3) rcp[l] = 1 / sum_m E2[m,l]
    colsum_kernel<<<dim3(4, 16, BATCH), 256>>>();
    reduce_rcp_kernel<<<BATCH, 1024>>>();

    // 4) y'[d,l] = (Wp[d,:]·xTh[l,:]) * rcp[l]   K=1024, half out
    hgemm_kernel<4, __half><<<dim3(LDIM / BN, CDIM / BM, BATCH), 128, SMEM>>>(
        p_wph, p_xTh, p_rcp, p_y,
        CDIM, CDIM, CDIM, LDIM,
        0LL, (long long)LDIM * CDIM, (long long)CDIM * LDIM);

    // 5) out[d,m] = y'[d,:]·E2[m,:] + bp[d]   K=2048, f32 out
    hgemm_kernel<3, float><<<dim3(LDIM / BN, CDIM / BM, BATCH), 128, SMEM>>>(
        p_y, p_E2, bp, out,
        LDIM, LDIM, LDIM, LDIM,
        (long long)CDIM * LDIM, (long long)LDIM * LDIM, (long long)CDIM * LDIM);
}